// round 13
// baseline (speedup 1.0000x reference)
#include <cuda_runtime.h>

namespace {

constexpr int MAXB = 2048;
constexpr int THREADS = 128;   // 4 warps = 16 groups of 8 lanes

__device__ __align__(16) float g_W1p[27 * 128];   // W1 transposed: [k][j]
__device__ __align__(16) float g_Wsum[9 * 128];   // W1p[d]+W1p[9+d]+W1p[18+d]
__device__ float4 g_zs[(size_t)MAXB * 81 * 32];   // z scratch: [b][c][j]

__global__ void prep_kernel(const float* __restrict__ W1) {
    int j = threadIdx.x;  // 0..127
    #pragma unroll
    for (int k = 0; k < 27; k++) g_W1p[k * 128 + j] = W1[j * 27 + k];
    #pragma unroll
    for (int d = 0; d < 9; d++)
        g_Wsum[d * 128 + j] = W1[j * 27 + d] + W1[j * 27 + 9 + d] + W1[j * 27 + 18 + d];
}

__device__ __forceinline__ unsigned redux_maxu(unsigned v) {
    unsigned r; asm("redux.sync.max.u32 %0, %1, 0xffffffff;" : "=r"(r) : "r"(v)); return r;
}
__device__ __forceinline__ unsigned redux_minu(unsigned v) {
    unsigned r; asm("redux.sync.min.u32 %0, %1, 0xffffffff;" : "=r"(r) : "r"(v)); return r;
}

__global__ __launch_bounds__(THREADS, 9)
void sudoku_kernel(const float* __restrict__ x,
                   const float* __restrict__ W2,
                   float* __restrict__ out)
{
    __shared__ float4 w2s[288];           // W2 as float4: w2s[e*32+j]
    __shared__ float cnt[3][9][9];
    __shared__ float score_s[96];         // 81 used; padding reads 0
    __shared__ int   pos_s[81];
    __shared__ unsigned char emptyb[81];
    __shared__ unsigned char empty0[81];
    __shared__ int   sel_md;              // packed m | (d<<8), or -1 = done

    const int tid  = threadIdx.x;
    const int lane = tid & 31;
    const int wid  = tid >> 5;
    const int grp  = tid >> 3;            // 0..15
    const int gl   = tid & 7;             // lane-in-group; owns float4s k*8+gl
    const unsigned gmask = 0xFFu << (lane & 24);   // this group's 8 lanes
    const long long b = blockIdx.x;
    const float* xb = x + b * 729;
    float* ob = out + b * 729;
    float4* zb = g_zs + (size_t)b * 81 * 32;

    for (int i = tid; i < 288; i += THREADS) w2s[i] = ((const float4*)W2)[i];
    for (int i = tid; i < 243; i += THREADS) (&cnt[0][0][0])[i] = 0.f;
    for (int i = tid; i < 729; i += THREADS) ob[i] = xb[i];   // x_pred init = x
    if (tid < 96) score_s[tid] = 0.f;
    __syncthreads();

    if (tid < 81) {
        int d = -1;
        #pragma unroll
        for (int e = 0; e < 9; e++)
            if (xb[tid * 9 + e] > 0.5f) d = e;
        pos_s[tid] = 0;
        if (d >= 0) {
            emptyb[tid] = 0; empty0[tid] = 0;
            int r = tid / 9, cc = tid % 9, bx = (r / 3) * 3 + cc / 3;
            atomicAdd(&cnt[0][r][d],  1.f);
            atomicAdd(&cnt[1][cc][d], 1.f);
            atomicAdd(&cnt[2][bx][d], 1.f);
        } else {
            emptyb[tid] = 1; empty0[tid] = 1;
        }
    }
    __syncthreads();

    // relu + y = h @ W2^T (this lane's 16 h-units) + 3-round group butterfly.
    auto reduce8 = [&](float4 z4[4], float p[9]) {
        #pragma unroll
        for (int k = 0; k < 4; k++) {
            z4[k].x = fmaxf(z4[k].x, 0.f); z4[k].y = fmaxf(z4[k].y, 0.f);
            z4[k].z = fmaxf(z4[k].z, 0.f); z4[k].w = fmaxf(z4[k].w, 0.f);
        }
        #pragma unroll
        for (int e = 0; e < 9; e++) {
            float a = 0.f;
            #pragma unroll
            for (int k = 0; k < 4; k++) {
                float4 w = w2s[e * 32 + k * 8 + gl];
                a = fmaf(z4[k].x, w.x, a); a = fmaf(z4[k].y, w.y, a);
                a = fmaf(z4[k].z, w.z, a); a = fmaf(z4[k].w, w.w, a);
            }
            p[e] = a;
        }
        #pragma unroll
        for (int off = 4; off > 0; off >>= 1) {
            #pragma unroll
            for (int e = 0; e < 9; e++)
                p[e] += __shfl_xor_sync(gmask, p[e], off);
        }
    };

    // Bit-identical to R11: per-lane redundant softmax score (SIMD-free redundancy).
    auto scorepos8 = [&](int c, const float p[9]) {
        float mx = p[0];
        #pragma unroll
        for (int e = 1; e < 9; e++) mx = fmaxf(mx, p[e]);
        float sum = 0.f, best = -1.f; int bp = 0;
        #pragma unroll
        for (int e = 0; e < 9; e++) {
            float q = __expf(p[e] - mx);
            sum += q;
            if (q > best) { best = q; bp = e; }   // strict > = first max
        }
        if (gl == 0) { score_s[c] = __fdividef(best, sum); pos_s[c] = bp; }
    };

    auto map_cell = [](int i, int rm, int cm3, int brm) -> int {
        if (i < 3)  return 3 * rm + i;
        if (i < 12) return 27 + 3 * (i - 3) + cm3;
        return 54 + 3 * (brm + (i - 12)) + cm3;
    };

    // ---- Initial pass: 16 groups over each 27-cell type region ----
    for (int base = 0; base < 27; base += 16) {
        int cc = base + grp;
        if (cc < 27 && emptyb[cc]) {
            const float* f = cnt[0][cc / 3];
            float4 z4[4] = {};
            #pragma unroll
            for (int e = 0; e < 9; e++) {
                float fv = f[e];
                #pragma unroll
                for (int k = 0; k < 4; k++) {
                    float4 w = __ldg((const float4*)(g_Wsum + e * 128) + k * 8 + gl);
                    z4[k].x = fmaf(fv, w.x, z4[k].x); z4[k].y = fmaf(fv, w.y, z4[k].y);
                    z4[k].z = fmaf(fv, w.z, z4[k].z); z4[k].w = fmaf(fv, w.w, z4[k].w);
                }
            }
            #pragma unroll
            for (int k = 0; k < 4; k++) zb[cc * 32 + k * 8 + gl] = z4[k];
            float p[9]; reduce8(z4, p);
            scorepos8(cc, p);
        }
    }
    for (int base = 0; base < 27; base += 16) {
        int cc = base + grp;
        if (cc < 27 && emptyb[cc + 27]) {
            int g0 = 3 * (cc % 3);
            float4 z4[4] = {};
            #pragma unroll
            for (int blk = 0; blk < 3; blk++) {
                const float* f = cnt[1][g0 + blk];
                #pragma unroll
                for (int e = 0; e < 9; e++) {
                    float fv = f[e];
                    #pragma unroll
                    for (int k = 0; k < 4; k++) {
                        float4 w = __ldg((const float4*)(g_W1p + (9 * blk + e) * 128) + k * 8 + gl);
                        z4[k].x = fmaf(fv, w.x, z4[k].x); z4[k].y = fmaf(fv, w.y, z4[k].y);
                        z4[k].z = fmaf(fv, w.z, z4[k].z); z4[k].w = fmaf(fv, w.w, z4[k].w);
                    }
                }
            }
            int co = cc + 27;
            #pragma unroll
            for (int k = 0; k < 4; k++) zb[co * 32 + k * 8 + gl] = z4[k];
            float p[9]; reduce8(z4, p);
            scorepos8(co, p);
        }
    }
    for (int base = 0; base < 27; base += 16) {
        int cc = base + grp;
        if (cc < 27 && emptyb[cc + 54]) {
            const float* f = cnt[2][3 * (cc / 9) + cc % 3];
            float4 z4[4] = {};
            #pragma unroll
            for (int e = 0; e < 9; e++) {
                float fv = f[e];
                #pragma unroll
                for (int k = 0; k < 4; k++) {
                    float4 w = __ldg((const float4*)(g_Wsum + e * 128) + k * 8 + gl);
                    z4[k].x = fmaf(fv, w.x, z4[k].x); z4[k].y = fmaf(fv, w.y, z4[k].y);
                    z4[k].z = fmaf(fv, w.z, z4[k].z); z4[k].w = fmaf(fv, w.w, z4[k].w);
                }
            }
            int co = cc + 54;
            #pragma unroll
            for (int k = 0; k < 4; k++) zb[co * 32 + k * 8 + gl] = z4[k];
            float p[9]; reduce8(z4, p);
            scorepos8(co, p);
        }
    }
    __syncthreads();

    // ---- Sequential fill loop: warp-0-only selection; two barriers/iter ----
    for (int iter = 0; iter < 81; ++iter) {
        if (wid == 0) {
            float s0 = score_s[lane];
            float s1 = score_s[lane + 32];
            float s2 = score_s[lane + 64];
            unsigned bb = __float_as_uint(s0); int bi = lane;
            unsigned v1 = __float_as_uint(s1); if (v1 > bb) { bb = v1; bi = lane + 32; }
            unsigned v2 = __float_as_uint(s2); if (v2 > bb) { bb = v2; bi = lane + 64; }
            unsigned wmax = redux_maxu(bb);
            unsigned cand = (bb == wmax) ? (unsigned)bi : 0xFFu;
            int m = (int)redux_minu(cand);
            if (lane == 0)
                sel_md = (wmax == 0u) ? -1 : (m | (pos_s[m] << 8));
        }
        __syncthreads();   // B: broadcast selection

        const int sel = sel_md;
        if (sel < 0) break;
        const int m = sel & 0xFF, d = sel >> 8;

        const int rm = m / 9, cm = m % 9;
        const int cm3 = cm / 3, brm = (rm / 3) * 3;

        int cl = map_cell(lane < 15 ? lane : 0, rm, cm3, brm);
        bool pr = (lane < 15) && (cl != m) && emptyb[cl];
        unsigned mask = __ballot_sync(0xffffffffu, pr);
        int ne = __popc(mask);              // <= 14 < 16 groups

        if (tid == 0) { emptyb[m] = 0; score_s[m] = 0.f; }  // next read after barrier B

        if (grp < ne) {                     // group-granular divergence
            int bit = (int)__fns(mask, 0, grp + 1);
            int c   = map_cell(bit, rm, cm3, brm);
            const float* wrow = (bit >= 3 && bit < 12)
                              ? g_W1p + (9 * (cm % 3) + d) * 128
                              : g_Wsum + d * 128;
            float4 z4[4];
            #pragma unroll
            for (int k = 0; k < 4; k++) {
                float4 z = zb[c * 32 + k * 8 + gl];
                float4 w = __ldg((const float4*)wrow + k * 8 + gl);
                z.x += w.x; z.y += w.y; z.z += w.z; z.w += w.w;
                z4[k] = z;
            }
            #pragma unroll
            for (int k = 0; k < 4; k++) zb[c * 32 + k * 8 + gl] = z4[k];
            float p[9]; reduce8(z4, p);
            scorepos8(c, p);
        }

        __syncthreads();   // A: publish z/score/pos + m-clears before next selection
    }
    __syncthreads();

    // ---- Final pass: softmax of frozen z for initially-empty cells ----
    for (int base = 0; base < 81; base += 16) {
        int c = base + grp;
        if (c < 81 && empty0[c]) {
            float4 z4[4];
            #pragma unroll
            for (int k = 0; k < 4; k++) z4[k] = zb[c * 32 + k * 8 + gl];
            float p[9]; reduce8(z4, p);
            float mx = p[0];
            #pragma unroll
            for (int e = 1; e < 9; e++) mx = fmaxf(mx, p[e]);
            float sum = 0.f;
            #pragma unroll
            for (int e = 0; e < 9; e++) { p[e] = __expf(p[e] - mx); sum += p[e]; }
            ob[c * 9 + gl] = __fdividef(p[gl], sum);
            if (gl == 0) ob[c * 9 + 8] = __fdividef(p[8], sum);
        }
    }
}

} // namespace

extern "C" void kernel_launch(void* const* d_in, const int* in_sizes, int n_in,
                              void* d_out, int out_size) {
    const float* x  = (const float*)d_in[0];
    const float* W1 = (const float*)d_in[1];
    const float* W2 = (const float*)d_in[2];
    float* out = (float*)d_out;
    int B = in_sizes[0] / 729;
    prep_kernel<<<1, 128>>>(W1);
    sudoku_kernel<<<B, THREADS>>>(x, W2, out);
}

// round 14
// speedup vs baseline: 1.0697x; 1.0697x over previous
#include <cuda_runtime.h>

namespace {

typedef unsigned long long u64;

constexpr int MAXB = 2048;
constexpr int THREADS = 128;   // 4 warps = 16 groups of 8 lanes

__device__ __align__(16) float g_W1p[27 * 128];   // W1 transposed: [k][j]
__device__ __align__(16) float g_Wsum[9 * 128];   // W1p[d]+W1p[9+d]+W1p[18+d]
__device__ float4 g_zs[(size_t)MAXB * 81 * 32];   // z scratch: [b][c][j]

__global__ void prep_kernel(const float* __restrict__ W1) {
    int j = threadIdx.x;  // 0..127
    #pragma unroll
    for (int k = 0; k < 27; k++) g_W1p[k * 128 + j] = W1[j * 27 + k];
    #pragma unroll
    for (int d = 0; d < 9; d++)
        g_Wsum[d * 128 + j] = W1[j * 27 + d] + W1[j * 27 + 9 + d] + W1[j * 27 + 18 + d];
}

__device__ __forceinline__ unsigned redux_maxu(unsigned v) {
    unsigned r; asm("redux.sync.max.u32 %0, %1, 0xffffffff;" : "=r"(r) : "r"(v)); return r;
}
__device__ __forceinline__ unsigned redux_minu(unsigned v) {
    unsigned r; asm("redux.sync.min.u32 %0, %1, 0xffffffff;" : "=r"(r) : "r"(v)); return r;
}
// Packed two-float ops (sm_103a FFMA2/FADD2; PTX-only, ptxas never auto-fuses)
__device__ __forceinline__ u64 ffma2(u64 a, u64 b, u64 c) {
    u64 d; asm("fma.rn.f32x2 %0, %1, %2, %3;" : "=l"(d) : "l"(a), "l"(b), "l"(c)); return d;
}
__device__ __forceinline__ u64 fadd2(u64 a, u64 b) {
    u64 d; asm("add.rn.f32x2 %0, %1, %2;" : "=l"(d) : "l"(a), "l"(b)); return d;
}
__device__ __forceinline__ u64 bcast2(float v) {
    unsigned u = __float_as_uint(v);
    return ((u64)u << 32) | u;
}
__device__ __forceinline__ float lo2(u64 v) { return __uint_as_float((unsigned)v); }
__device__ __forceinline__ float hi2(u64 v) { return __uint_as_float((unsigned)(v >> 32)); }
__device__ __forceinline__ u64 pack2(float lo, float hi) {
    return ((u64)__float_as_uint(hi) << 32) | __float_as_uint(lo);
}

__global__ __launch_bounds__(THREADS)
void sudoku_kernel(const float* __restrict__ x,
                   const float* __restrict__ W2,
                   float* __restrict__ out)
{
    __shared__ __align__(16) float w2s[288 * 4];  // W2: w2s[(e*32+j)*4 ..]
    __shared__ float cnt[3][9][9];
    __shared__ float score_s[96];         // 81 used; padding reads 0
    __shared__ int   pos_s[81];
    __shared__ unsigned char emptyb[81];
    __shared__ unsigned char empty0[81];

    const int tid  = threadIdx.x;
    const int lane = tid & 31;
    const int grp  = tid >> 3;            // 0..15
    const int gl   = tid & 7;             // lane-in-group; owns float4s k*8+gl
    const unsigned gmask = 0xFFu << (lane & 24);   // this group's 8 lanes
    const long long b = blockIdx.x;
    const float* xb = x + b * 729;
    float* ob = out + b * 729;
    float4* zb = g_zs + (size_t)b * 81 * 32;
    ulonglong2* zbu = (ulonglong2*)zb;

    for (int i = tid; i < 288; i += THREADS)
        ((float4*)w2s)[i] = ((const float4*)W2)[i];
    for (int i = tid; i < 243; i += THREADS) (&cnt[0][0][0])[i] = 0.f;
    for (int i = tid; i < 729; i += THREADS) ob[i] = xb[i];   // x_pred init = x
    if (tid < 96) score_s[tid] = 0.f;
    __syncthreads();

    if (tid < 81) {
        int d = -1;
        #pragma unroll
        for (int e = 0; e < 9; e++)
            if (xb[tid * 9 + e] > 0.5f) d = e;
        pos_s[tid] = 0;
        if (d >= 0) {
            emptyb[tid] = 0; empty0[tid] = 0;
            int r = tid / 9, cc = tid % 9, bx = (r / 3) * 3 + cc / 3;
            atomicAdd(&cnt[0][r][d],  1.f);
            atomicAdd(&cnt[1][cc][d], 1.f);
            atomicAdd(&cnt[2][bx][d], 1.f);
        } else {
            emptyb[tid] = 1; empty0[tid] = 1;
        }
    }
    __syncthreads();

    // relu (scalar on pair-halves; pack/unpack = register aliasing) +
    // y = h @ W2^T via FFMA2 + 3-round group butterfly.
    auto reduce8 = [&](const u64 zz[8], float p[9]) {
        u64 h2[8];
        #pragma unroll
        for (int i = 0; i < 8; i++)
            h2[i] = pack2(fmaxf(lo2(zz[i]), 0.f), fmaxf(hi2(zz[i]), 0.f));
        #pragma unroll
        for (int e = 0; e < 9; e++) {
            u64 acc = 0ull;   // packed (0,0)
            #pragma unroll
            for (int k = 0; k < 4; k++) {
                ulonglong2 w = ((const ulonglong2*)w2s)[e * 32 + k * 8 + gl];
                acc = ffma2(h2[2 * k],     w.x, acc);
                acc = ffma2(h2[2 * k + 1], w.y, acc);
            }
            p[e] = lo2(acc) + hi2(acc);
        }
        #pragma unroll
        for (int off = 4; off > 0; off >>= 1) {
            #pragma unroll
            for (int e = 0; e < 9; e++)
                p[e] += __shfl_xor_sync(gmask, p[e], off);
        }
    };

    // Bit-identical to R11: per-lane redundant softmax score.
    auto scorepos8 = [&](int c, const float p[9]) {
        float mx = p[0];
        #pragma unroll
        for (int e = 1; e < 9; e++) mx = fmaxf(mx, p[e]);
        float sum = 0.f, best = -1.f; int bp = 0;
        #pragma unroll
        for (int e = 0; e < 9; e++) {
            float q = __expf(p[e] - mx);
            sum += q;
            if (q > best) { best = q; bp = e; }   // strict > = first max
        }
        if (gl == 0) { score_s[c] = __fdividef(best, sum); pos_s[c] = bp; }
    };

    auto store_z = [&](int c, const u64 zz[8]) {
        #pragma unroll
        for (int k = 0; k < 4; k++) {
            ulonglong2 v; v.x = zz[2 * k]; v.y = zz[2 * k + 1];
            zbu[c * 32 + k * 8 + gl] = v;
        }
    };

    auto map_cell = [](int i, int rm, int cm3, int brm) -> int {
        if (i < 3)  return 3 * rm + i;
        if (i < 12) return 27 + 3 * (i - 3) + cm3;
        return 54 + 3 * (brm + (i - 12)) + cm3;
    };

    // ---- Initial pass: 16 groups over each 27-cell type region ----
    for (int base = 0; base < 27; base += 16) {
        int cc = base + grp;
        if (cc < 27 && emptyb[cc]) {
            const float* f = cnt[0][cc / 3];
            u64 zz[8] = {};
            #pragma unroll
            for (int e = 0; e < 9; e++) {
                u64 fv2 = bcast2(f[e]);
                #pragma unroll
                for (int k = 0; k < 4; k++) {
                    ulonglong2 w = ((const ulonglong2*)(g_Wsum + e * 128))[k * 8 + gl];
                    zz[2 * k]     = ffma2(fv2, w.x, zz[2 * k]);
                    zz[2 * k + 1] = ffma2(fv2, w.y, zz[2 * k + 1]);
                }
            }
            store_z(cc, zz);
            float p[9]; reduce8(zz, p);
            scorepos8(cc, p);
        }
    }
    for (int base = 0; base < 27; base += 16) {
        int cc = base + grp;
        if (cc < 27 && emptyb[cc + 27]) {
            int g0 = 3 * (cc % 3);
            u64 zz[8] = {};
            #pragma unroll
            for (int blk = 0; blk < 3; blk++) {
                const float* f = cnt[1][g0 + blk];
                #pragma unroll
                for (int e = 0; e < 9; e++) {
                    u64 fv2 = bcast2(f[e]);
                    #pragma unroll
                    for (int k = 0; k < 4; k++) {
                        ulonglong2 w = ((const ulonglong2*)(g_W1p + (9 * blk + e) * 128))[k * 8 + gl];
                        zz[2 * k]     = ffma2(fv2, w.x, zz[2 * k]);
                        zz[2 * k + 1] = ffma2(fv2, w.y, zz[2 * k + 1]);
                    }
                }
            }
            int co = cc + 27;
            store_z(co, zz);
            float p[9]; reduce8(zz, p);
            scorepos8(co, p);
        }
    }
    for (int base = 0; base < 27; base += 16) {
        int cc = base + grp;
        if (cc < 27 && emptyb[cc + 54]) {
            const float* f = cnt[2][3 * (cc / 9) + cc % 3];
            u64 zz[8] = {};
            #pragma unroll
            for (int e = 0; e < 9; e++) {
                u64 fv2 = bcast2(f[e]);
                #pragma unroll
                for (int k = 0; k < 4; k++) {
                    ulonglong2 w = ((const ulonglong2*)(g_Wsum + e * 128))[k * 8 + gl];
                    zz[2 * k]     = ffma2(fv2, w.x, zz[2 * k]);
                    zz[2 * k + 1] = ffma2(fv2, w.y, zz[2 * k + 1]);
                }
            }
            int co = cc + 54;
            store_z(co, zz);
            float p[9]; reduce8(zz, p);
            scorepos8(co, p);
        }
    }
    __syncthreads();

    // ---- Sequential fill loop: ONE barrier/iter; selection redundant per warp;
    //      all <=14 affected cells in ONE parallel pass (16 groups). ----
    for (int iter = 0; iter < 81; ++iter) {
        float s0 = score_s[lane];
        float s1 = score_s[lane + 32];
        float s2 = score_s[lane + 64];
        unsigned bb = __float_as_uint(s0); int bi = lane;
        unsigned v1 = __float_as_uint(s1); if (v1 > bb) { bb = v1; bi = lane + 32; }
        unsigned v2 = __float_as_uint(s2); if (v2 > bb) { bb = v2; bi = lane + 64; }
        unsigned wmax = redux_maxu(bb);
        if (wmax == 0u) break;              // CTA-uniform
        unsigned cand = (bb == wmax) ? (unsigned)bi : 0xFFu;
        const int m = (int)redux_minu(cand);
        const int d = pos_s[m];

        const int rm = m / 9, cm = m % 9;
        const int cm3 = cm / 3, brm = (rm / 3) * 3;

        int cl = map_cell(lane < 15 ? lane : 0, rm, cm3, brm);
        bool pr = (lane < 15) && (cl != m) && emptyb[cl];
        unsigned mask = __ballot_sync(0xffffffffu, pr);
        int ne = __popc(mask);              // <= 14 < 16 groups

        if (tid == 0) { emptyb[m] = 0; score_s[m] = 0.f; }  // read after barrier only

        if (grp < ne) {                     // group-granular divergence
            int bit = (int)__fns(mask, 0, grp + 1);
            int c   = map_cell(bit, rm, cm3, brm);
            const float* wrow = (bit >= 3 && bit < 12)
                              ? g_W1p + (9 * (cm % 3) + d) * 128
                              : g_Wsum + d * 128;
            u64 zz[8];
            #pragma unroll
            for (int k = 0; k < 4; k++) {
                ulonglong2 z = zbu[c * 32 + k * 8 + gl];
                ulonglong2 w = ((const ulonglong2*)wrow)[k * 8 + gl];
                zz[2 * k]     = fadd2(z.x, w.x);
                zz[2 * k + 1] = fadd2(z.y, w.y);
            }
            store_z(c, zz);
            float p[9]; reduce8(zz, p);
            scorepos8(c, p);
        }

        __syncthreads();   // publish z/score/pos + m-clears to all warps
    }
    __syncthreads();

    // ---- Final pass: softmax of frozen z for initially-empty cells ----
    for (int base = 0; base < 81; base += 16) {
        int c = base + grp;
        if (c < 81 && empty0[c]) {
            u64 zz[8];
            #pragma unroll
            for (int k = 0; k < 4; k++) {
                ulonglong2 z = zbu[c * 32 + k * 8 + gl];
                zz[2 * k] = z.x; zz[2 * k + 1] = z.y;
            }
            float p[9]; reduce8(zz, p);
            float mx = p[0];
            #pragma unroll
            for (int e = 1; e < 9; e++) mx = fmaxf(mx, p[e]);
            float sum = 0.f;
            #pragma unroll
            for (int e = 0; e < 9; e++) { p[e] = __expf(p[e] - mx); sum += p[e]; }
            ob[c * 9 + gl] = __fdividef(p[gl], sum);
            if (gl == 0) ob[c * 9 + 8] = __fdividef(p[8], sum);
        }
    }
}

} // namespace

extern "C" void kernel_launch(void* const* d_in, const int* in_sizes, int n_in,
                              void* d_out, int out_size) {
    const float* x  = (const float*)d_in[0];
    const float* W1 = (const float*)d_in[1];
    const float* W2 = (const float*)d_in[2];
    float* out = (float*)d_out;
    int B = in_sizes[0] / 729;
    prep_kernel<<<1, 128>>>(W1);
    sudoku_kernel<<<B, THREADS>>>(x, W2, out);
}